// round 2
// baseline (speedup 1.0000x reference)
#include <cuda_runtime.h>
#include <cstdint>

#define KTAPS 27
#define CIN   32
#define COUT  32
#define TILE  256
#define NTHR  256
#define NB    8      // n_batch (reference constant)
#define GRP   8
#define GEPS  1e-5f

#define W_STRIDE 36  // padded ci-stride for transposed weights  -> conflict-free B frags
#define X_STRIDE 36  // padded row stride for x tile             -> conflict-free A frags + 16B cp.async
#define SW_WORDS (KTAPS * COUT * W_STRIDE)   // 31104
#define SX_WORDS (TILE * X_STRIDE)           // 9216 (one buffer)
#define SN_WORDS (TILE * KTAPS)              // 6912
#define SMEM_WORDS (SW_WORDS + 2 * SX_WORDS + SN_WORDS)
#define SMEM_BYTES (SMEM_WORDS * 4)          // 225792 B

// ---------------- device-global scratch (no allocations allowed) ----------------
__device__ float gS [NB * COUT];
__device__ float gSS[NB * COUT];
__device__ float gCnt[NB];
__device__ float gMean[NB * GRP];
__device__ float gIstd[NB * GRP];

// ---------------- small PTX helpers ----------------
__device__ __forceinline__ uint32_t f2tf32(float f) {
    uint32_t r;
    asm("cvt.rna.tf32.f32 %0, %1;" : "=r"(r) : "f"(f));
    return r;
}

__device__ __forceinline__ void cp_async16(uint32_t smem_addr, const void* gptr) {
    asm volatile("cp.async.cg.shared.global [%0], [%1], 16;\n"
                 :: "r"(smem_addr), "l"(gptr));
}
__device__ __forceinline__ void cp_async_commit() {
    asm volatile("cp.async.commit_group;\n");
}
template <int N>
__device__ __forceinline__ void cp_async_wait() {
    asm volatile("cp.async.wait_group %0;\n" :: "n"(N));
}

__device__ __forceinline__ void mma_tf32(float* d, const uint32_t* a, uint32_t b0, uint32_t b1) {
    asm volatile(
        "mma.sync.aligned.m16n8k8.row.col.f32.tf32.tf32.f32 "
        "{%0,%1,%2,%3}, {%4,%5,%6,%7}, {%8,%9}, {%0,%1,%2,%3};"
        : "+f"(d[0]), "+f"(d[1]), "+f"(d[2]), "+f"(d[3])
        : "r"(a[0]), "r"(a[1]), "r"(a[2]), "r"(a[3]), "r"(b0), "r"(b1));
}

// ---------------- kernel 0: zero stats ----------------
__global__ void zero_stats_kernel() {
    int t = threadIdx.x;
    if (t < NB * COUT) { gS[t] = 0.f; gSS[t] = 0.f; }
    if (t < NB) gCnt[t] = 0.f;
}

// ---------------- kernel 1: deconv (tf32 tensor-core GEMM over gathered taps) ----------------
__global__ __launch_bounds__(NTHR, 1)
void deconv_kernel(const float* __restrict__ data,
                   const float* __restrict__ weights,
                   const int*   __restrict__ neigh,
                   float* __restrict__ out, int N)
{
    extern __shared__ float smem[];
    uint32_t* sW = (uint32_t*)smem;                 // [27][co=32][ci stride 36], tf32 bits
    float*    sX = smem + SW_WORDS;                 // 2 x [256][36]
    int*      sN = (int*)(smem + SW_WORDS + 2 * SX_WORDS);

    const int tid  = threadIdx.x;
    const int lane = tid & 31;
    const int warp = tid >> 5;
    const int blockStart = blockIdx.x * TILE;
    const int nodesHere  = min(TILE, N - blockStart);

    // ---- stage weights: transpose [k][ci][co] -> [k][co][ci], cvt.rna to tf32 ----
    const float4* w4 = (const float4*)weights;
    for (int q = tid; q < (KTAPS * CIN * COUT) / 4; q += NTHR) {
        float4 v = w4[q];
        int lin = q * 4;
        int k  = lin >> 10;
        int r  = lin & 1023;
        int ci = r >> 5;
        int co = r & 31;
        uint32_t* dst = sW + k * (COUT * W_STRIDE) + ci;
        dst[(co + 0) * W_STRIDE] = f2tf32(v.x);
        dst[(co + 1) * W_STRIDE] = f2tf32(v.y);
        dst[(co + 2) * W_STRIDE] = f2tf32(v.z);
        dst[(co + 3) * W_STRIDE] = f2tf32(v.w);
    }

    // ---- stage neighbor table for the tile (coalesced) ----
    const int nlim = nodesHere * KTAPS;
    for (int i = tid; i < TILE * KTAPS; i += NTHR)
        sN[i] = (i < nlim) ? neigh[blockStart * KTAPS + i] : 0;
    __syncthreads();

    // ---- accumulators: warp covers rows [warp*32, warp*32+32), all 32 couts ----
    float acc[2][4][4];
    #pragma unroll
    for (int m = 0; m < 2; m++)
        #pragma unroll
        for (int nt = 0; nt < 4; nt++)
            #pragma unroll
            for (int j = 0; j < 4; j++) acc[m][nt][j] = 0.f;

    const int g = lane >> 2;
    const int c = lane & 3;
    const int rowbase = warp * 32 + g;

    // ---- prefetch tap 0 ----
    {
        int idx = (tid < nodesHere) ? sN[tid * KTAPS + 0] : 0;
        const float* src = data + (size_t)idx * CIN;
        uint32_t sa = (uint32_t)__cvta_generic_to_shared(sX + 0 * SX_WORDS + tid * X_STRIDE);
        #pragma unroll
        for (int q = 0; q < 8; q++) cp_async16(sa + q * 16, src + q * 4);
        cp_async_commit();
    }

    for (int k = 0; k < KTAPS; k++) {
        if (k + 1 < KTAPS) {
            int idx = (tid < nodesHere) ? sN[tid * KTAPS + (k + 1)] : 0;
            const float* src = data + (size_t)idx * CIN;
            uint32_t sa = (uint32_t)__cvta_generic_to_shared(
                sX + ((k + 1) & 1) * SX_WORDS + tid * X_STRIDE);
            #pragma unroll
            for (int q = 0; q < 8; q++) cp_async16(sa + q * 16, src + q * 4);
            cp_async_commit();
            cp_async_wait<1>();          // tap k arrived
        } else {
            cp_async_wait<0>();
        }
        __syncthreads();                 // tap-k buffer visible to all

        const uint32_t* xw = (const uint32_t*)(sX + (k & 1) * SX_WORDS);
        const uint32_t* wk = sW + k * (COUT * W_STRIDE);

        #pragma unroll
        for (int kc = 0; kc < 4; kc++) {
            uint32_t a[2][4];
            const int col = kc * 8 + c;
            #pragma unroll
            for (int m = 0; m < 2; m++) {
                int r0 = rowbase + m * 16;
                a[m][0] = xw[(r0    ) * X_STRIDE + col    ];
                a[m][1] = xw[(r0 + 8) * X_STRIDE + col    ];
                a[m][2] = xw[(r0    ) * X_STRIDE + col + 4];
                a[m][3] = xw[(r0 + 8) * X_STRIDE + col + 4];
            }
            #pragma unroll
            for (int nt = 0; nt < 4; nt++) {
                uint32_t b0 = wk[(nt * 8 + g) * W_STRIDE + kc * 8 + c    ];
                uint32_t b1 = wk[(nt * 8 + g) * W_STRIDE + kc * 8 + c + 4];
                mma_tf32(acc[0][nt], a[0], b0, b1);
                mma_tf32(acc[1][nt], a[1], b0, b1);
            }
        }
        __syncthreads();                 // all done reading buf before it is refilled
    }

    // ---- epilogue: write h (pre-norm) to out ----
    #pragma unroll
    for (int m = 0; m < 2; m++) {
        int r0 = rowbase + m * 16;
        #pragma unroll
        for (int nt = 0; nt < 4; nt++) {
            int colp = nt * 8 + 2 * c;
            int node0 = blockStart + r0;
            int node1 = node0 + 8;
            if (node0 < N) {
                float2 v = make_float2(acc[m][nt][0], acc[m][nt][1]);
                *(float2*)(out + (size_t)node0 * COUT + colp) = v;
            }
            if (node1 < N) {
                float2 v = make_float2(acc[m][nt][2], acc[m][nt][3]);
                *(float2*)(out + (size_t)node1 * COUT + colp) = v;
            }
        }
    }
}

// ---------------- kernel 2: per-(batch,channel) sum / sumsq / count ----------------
__global__ void stats_kernel(const float* __restrict__ h,
                             const int* __restrict__ batch_id,
                             int N, int span)
{
    const int co = threadIdx.x & 31;
    const int w  = blockIdx.x * (blockDim.x >> 5) + (threadIdx.x >> 5);
    long r0 = (long)w * span;
    long r1 = r0 + span; if (r1 > N) r1 = N;
    if (r0 >= r1) return;

    float aS = 0.f, aSS = 0.f, cnt = 0.f;
    int cur = -1;
    for (long r = r0; r < r1; r++) {
        int b = batch_id[r];
        if (b != cur) {
            if (cur >= 0) {
                atomicAdd(&gS [cur * COUT + co], aS);
                atomicAdd(&gSS[cur * COUT + co], aSS);
                if (co == 0) atomicAdd(&gCnt[cur], cnt);
            }
            cur = b; aS = 0.f; aSS = 0.f; cnt = 0.f;
        }
        float v = h[r * COUT + co];
        aS += v; aSS += v * v; cnt += 1.f;
    }
    if (cur >= 0) {
        atomicAdd(&gS [cur * COUT + co], aS);
        atomicAdd(&gSS[cur * COUT + co], aSS);
        if (co == 0) atomicAdd(&gCnt[cur], cnt);
    }
}

// ---------------- kernel 3: finalize group stats (ocnn OctreeGroupNorm math) ----------------
__global__ void finalize_kernel() {
    int t = threadIdx.x;
    if (t >= NB * GRP) return;
    int b = t >> 3, g = t & 7;
    float S = 0.f, SS = 0.f;
    #pragma unroll
    for (int j = 0; j < 4; j++) {
        S  += gS [b * COUT + g * 4 + j];
        SS += gSS[b * COUT + g * 4 + j];
    }
    float cntf = gCnt[b] * ((float)COUT / (float)GRP);   // n_nodes * C/G
    float inv  = 1.f / (cntf + GEPS);
    float mean = S * inv;
    float var  = (SS - 2.f * mean * S + cntf * mean * mean) * inv;
    gMean[t] = mean;
    gIstd[t] = rsqrtf(var + GEPS);
}

// ---------------- kernel 4: normalize + affine + relu (in-place) ----------------
__global__ void norm_kernel(float* __restrict__ out,
                            const int* __restrict__ batch_id,
                            const float* __restrict__ gamma,
                            const float* __restrict__ beta,
                            int N)
{
    int e4 = blockIdx.x * blockDim.x + threadIdx.x;   // float4 index
    long total4 = (long)N * (COUT / 4);
    if (e4 >= total4) return;
    int node  = e4 >> 3;            // 8 float4 per row
    int cbase = (e4 & 7) * 4;
    int b = batch_id[node];
    float4 v = ((const float4*)out)[e4];
    float r[4] = {v.x, v.y, v.z, v.w};
    #pragma unroll
    for (int j = 0; j < 4; j++) {
        int cc = cbase + j;
        int gg = cc >> 2;
        float m  = gMean[b * GRP + gg];
        float is = gIstd[b * GRP + gg];
        float y = (r[j] - m) * is * gamma[cc] + beta[cc];
        r[j] = fmaxf(y, 0.f);
    }
    ((float4*)out)[e4] = make_float4(r[0], r[1], r[2], r[3]);
}

// ---------------- launch ----------------
extern "C" void kernel_launch(void* const* d_in, const int* in_sizes, int n_in,
                              void* d_out, int out_size)
{
    const float* data    = (const float*)d_in[0];
    const float* weights = (const float*)d_in[1];
    const float* gamma   = (const float*)d_in[2];
    const float* beta    = (const float*)d_in[3];
    const int*   neigh   = (const int*)d_in[4];
    const int*   batch   = (const int*)d_in[5];
    float*       out     = (float*)d_out;

    const int N = in_sizes[0] / CIN;

    cudaFuncSetAttribute(deconv_kernel,
                         cudaFuncAttributeMaxDynamicSharedMemorySize, SMEM_BYTES);

    zero_stats_kernel<<<1, 256>>>();

    int nblk = (N + TILE - 1) / TILE;
    deconv_kernel<<<nblk, NTHR, SMEM_BYTES>>>(data, weights, neigh, out, N);

    const int statBlocks = 592;                      // 4 CTAs/SM-ish
    const int nWarps = statBlocks * (256 / 32);
    const int span = (N + nWarps - 1) / nWarps;
    stats_kernel<<<statBlocks, 256>>>(out, batch, N, span);

    finalize_kernel<<<1, 64>>>();

    long total4 = (long)N * (COUT / 4);
    int nb2 = (int)((total4 + 255) / 256);
    norm_kernel<<<nb2, 256>>>(out, batch, gamma, beta, N);
}

// round 7
// speedup vs baseline: 1.5903x; 1.5903x over previous
#include <cuda_runtime.h>
#include <cstdint>

#define KTAPS 27
#define CIN   32
#define COUT  32
#define TILE  256
#define NTHR  256
#define NB    8      // n_batch (reference constant)
#define GRP   8
#define GEPS  1e-5f

#define W_STRIDE 36                           // padded ci-stride for transposed weights -> conflict-free B frags
#define SW_WORDS (KTAPS * COUT * W_STRIDE)    // 31104
#define SX_WORDS (NTHR / 32 * 32 * 32)        // 8 warps x 32 rows x 32 words = 8192
#define SN_WORDS (TILE * KTAPS)               // 6912
#define SMEM_WORDS (SW_WORDS + SX_WORDS + SN_WORDS)
#define SMEM_BYTES (SMEM_WORDS * 4)           // 184832 B

// ---------------- device-global scratch (no allocations allowed) ----------------
__device__ float gS [NB * COUT];
__device__ float gSS[NB * COUT];
__device__ float gCnt[NB];
__device__ float gMean[NB * GRP];
__device__ float gIstd[NB * GRP];

// ---------------- small PTX helpers ----------------
__device__ __forceinline__ uint32_t f2tf32(float f) {
    uint32_t r;
    asm("cvt.rna.tf32.f32 %0, %1;" : "=r"(r) : "f"(f));
    return r;
}

__device__ __forceinline__ void mma_tf32(float* d, const uint32_t* a, uint32_t b0, uint32_t b1) {
    asm volatile(
        "mma.sync.aligned.m16n8k8.row.col.f32.tf32.tf32.f32 "
        "{%0,%1,%2,%3}, {%4,%5,%6,%7}, {%8,%9}, {%0,%1,%2,%3};"
        : "+f"(d[0]), "+f"(d[1]), "+f"(d[2]), "+f"(d[3])
        : "r"(a[0]), "r"(a[1]), "r"(a[2]), "r"(a[3]), "r"(b0), "r"(b1));
}

// ---------------- kernel 0: zero stats ----------------
__global__ void zero_stats_kernel() {
    int t = threadIdx.x;
    if (t < NB * COUT) { gS[t] = 0.f; gSS[t] = 0.f; }
    if (t < NB) gCnt[t] = 0.f;
}

// ---------------- kernel 1: deconv (tf32 tensor-core GEMM over gathered taps) ----------------
//
// Each warp owns 32 rows of the 256-row tile. Gather path per tap:
//   LDG.128 (4 random rows / warp instr, 8 lanes x 16B per row) -> regs
//   STS.128 into a per-warp XOR-swizzled smem slab (stride 32 words, col ^ 4*(row&7))
//   LDS.32 A-frags + LDS.32 B-frags -> 32x mma.m16n8k8.tf32
// No CTA-wide barriers in the tap loop; LDG of tap k+1 overlaps MMAs of tap k.
__global__ __launch_bounds__(NTHR, 1)
void deconv_kernel(const float* __restrict__ data,
                   const float* __restrict__ weights,
                   const int*   __restrict__ neigh,
                   float* __restrict__ out, int N)
{
    extern __shared__ float smem[];
    uint32_t* sW = (uint32_t*)smem;                 // [27][co=32][ci stride 36], tf32 bits
    float*    sX = smem + SW_WORDS;                 // 8 warps x [32 rows][32 words], XOR swizzled
    int*      sN = (int*)(smem + SW_WORDS + SX_WORDS);

    const int tid  = threadIdx.x;
    const int lane = tid & 31;
    const int warp = tid >> 5;
    const int blockStart = blockIdx.x * TILE;
    const int nodesHere  = min(TILE, N - blockStart);

    // ---- stage weights: transpose [k][ci][co] -> [k][co][ci], cvt.rna to tf32 ----
    const float4* w4 = (const float4*)weights;
    for (int q = tid; q < (KTAPS * CIN * COUT) / 4; q += NTHR) {
        float4 v = w4[q];
        int lin = q * 4;
        int k  = lin >> 10;
        int r  = lin & 1023;
        int ci = r >> 5;
        int co = r & 31;
        uint32_t* dst = sW + k * (COUT * W_STRIDE) + ci;
        dst[(co + 0) * W_STRIDE] = f2tf32(v.x);
        dst[(co + 1) * W_STRIDE] = f2tf32(v.y);
        dst[(co + 2) * W_STRIDE] = f2tf32(v.z);
        dst[(co + 3) * W_STRIDE] = f2tf32(v.w);
    }

    // ---- stage neighbor table for the tile (coalesced); pad tail with 0 ----
    const int nlim = nodesHere * KTAPS;
    for (int i = tid; i < TILE * KTAPS; i += NTHR)
        sN[i] = (i < nlim) ? neigh[blockStart * KTAPS + i] : 0;
    __syncthreads();

    // ---- per-warp geometry ----
    const int g = lane >> 2;           // 0..7  (A/B row group)
    const int c = lane & 3;            // 0..3  (A/B col group)
    const int rsub = lane >> 3;        // 0..3  (gather: row-within-quad)
    const int cwrd = (lane & 7) * 4;   // gather: word col 0,4,...,28
    float*    myX  = sX + warp * (32 * 32);
    const int* myN = sN + (warp * 32) * KTAPS;

    float acc[2][4][4];
    #pragma unroll
    for (int m = 0; m < 2; m++)
        #pragma unroll
        for (int nt = 0; nt < 4; nt++)
            #pragma unroll
            for (int j = 0; j < 4; j++) acc[m][nt][j] = 0.f;

    // ---- gather staging registers: 8 x float4 per lane (rows 4i+rsub, 16B @ cwrd) ----
    float4 st[8];

    // prefetch tap 0
    #pragma unroll
    for (int i = 0; i < 8; i++) {
        int rl  = 4 * i + rsub;
        int idx = myN[rl * KTAPS + 0];
        st[i] = *(const float4*)(data + (size_t)idx * CIN + cwrd);
    }

    for (int k = 0; k < KTAPS; k++) {
        // store tap k regs -> swizzled smem (16B aligned; conflict-free quarter phases)
        #pragma unroll
        for (int i = 0; i < 8; i++) {
            int rl = 4 * i + rsub;
            int colw = cwrd ^ (4 * (rl & 7));
            *(float4*)(myX + rl * 32 + colw) = st[i];
        }
        // issue LDG for tap k+1 (overlaps with MMAs below)
        if (k + 1 < KTAPS) {
            #pragma unroll
            for (int i = 0; i < 8; i++) {
                int rl  = 4 * i + rsub;
                int idx = myN[rl * KTAPS + (k + 1)];
                st[i] = *(const float4*)(data + (size_t)idx * CIN + cwrd);
            }
        }
        __syncwarp();   // STS(k) visible to all lanes

        const uint32_t* xw = (const uint32_t*)myX;
        const uint32_t* wk = sW + k * (COUT * W_STRIDE);
        const int sw = 4 * g;

        #pragma unroll
        for (int kc = 0; kc < 4; kc++) {
            const int colA  = (kc * 8 + c)     ^ sw;
            const int colA2 = (kc * 8 + c + 4) ^ sw;
            uint32_t a[2][4];
            #pragma unroll
            for (int m = 0; m < 2; m++) {
                int r0 = g + 16 * m;
                a[m][0] = xw[(r0    ) * 32 + colA ];
                a[m][1] = xw[(r0 + 8) * 32 + colA ];
                a[m][2] = xw[(r0    ) * 32 + colA2];
                a[m][3] = xw[(r0 + 8) * 32 + colA2];
            }
            #pragma unroll
            for (int nt = 0; nt < 4; nt++) {
                uint32_t b0 = wk[(nt * 8 + g) * W_STRIDE + kc * 8 + c    ];
                uint32_t b1 = wk[(nt * 8 + g) * W_STRIDE + kc * 8 + c + 4];
                mma_tf32(acc[0][nt], a[0], b0, b1);
                mma_tf32(acc[1][nt], a[1], b0, b1);
            }
        }
        __syncwarp();   // all LDS(k) done before next iteration overwrites the slab
    }

    // ---- epilogue: write h (pre-norm) to out ----
    #pragma unroll
    for (int m = 0; m < 2; m++) {
        int r0 = warp * 32 + g + 16 * m;
        #pragma unroll
        for (int nt = 0; nt < 4; nt++) {
            int colp = nt * 8 + 2 * c;
            int node0 = blockStart + r0;
            int node1 = node0 + 8;
            if (node0 < N) {
                float2 v = make_float2(acc[m][nt][0], acc[m][nt][1]);
                *(float2*)(out + (size_t)node0 * COUT + colp) = v;
            }
            if (node1 < N) {
                float2 v = make_float2(acc[m][nt][2], acc[m][nt][3]);
                *(float2*)(out + (size_t)node1 * COUT + colp) = v;
            }
        }
    }
}

// ---------------- kernel 2: per-(batch,channel) sum / sumsq / count ----------------
__global__ void stats_kernel(const float* __restrict__ h,
                             const int* __restrict__ batch_id,
                             int N, int span)
{
    const int co = threadIdx.x & 31;
    const int w  = blockIdx.x * (blockDim.x >> 5) + (threadIdx.x >> 5);
    long r0 = (long)w * span;
    long r1 = r0 + span; if (r1 > N) r1 = N;
    if (r0 >= r1) return;

    float aS = 0.f, aSS = 0.f, cnt = 0.f;
    int cur = -1;
    for (long r = r0; r < r1; r++) {
        int b = batch_id[r];
        if (b != cur) {
            if (cur >= 0) {
                atomicAdd(&gS [cur * COUT + co], aS);
                atomicAdd(&gSS[cur * COUT + co], aSS);
                if (co == 0) atomicAdd(&gCnt[cur], cnt);
            }
            cur = b; aS = 0.f; aSS = 0.f; cnt = 0.f;
        }
        float v = h[r * COUT + co];
        aS += v; aSS += v * v; cnt += 1.f;
    }
    if (cur >= 0) {
        atomicAdd(&gS [cur * COUT + co], aS);
        atomicAdd(&gSS[cur * COUT + co], aSS);
        if (co == 0) atomicAdd(&gCnt[cur], cnt);
    }
}

// ---------------- kernel 3: finalize group stats (ocnn OctreeGroupNorm math) ----------------
__global__ void finalize_kernel() {
    int t = threadIdx.x;
    if (t >= NB * GRP) return;
    int b = t >> 3, g = t & 7;
    float S = 0.f, SS = 0.f;
    #pragma unroll
    for (int j = 0; j < 4; j++) {
        S  += gS [b * COUT + g * 4 + j];
        SS += gSS[b * COUT + g * 4 + j];
    }
    float cntf = gCnt[b] * ((float)COUT / (float)GRP);   // n_nodes * C/G
    float inv  = 1.f / (cntf + GEPS);
    float mean = S * inv;
    float var  = (SS - 2.f * mean * S + cntf * mean * mean) * inv;
    gMean[t] = mean;
    gIstd[t] = rsqrtf(var + GEPS);
}

// ---------------- kernel 4: normalize + affine + relu (in-place) ----------------
__global__ void norm_kernel(float* __restrict__ out,
                            const int* __restrict__ batch_id,
                            const float* __restrict__ gamma,
                            const float* __restrict__ beta,
                            int N)
{
    int e4 = blockIdx.x * blockDim.x + threadIdx.x;   // float4 index
    long total4 = (long)N * (COUT / 4);
    if (e4 >= total4) return;
    int node  = e4 >> 3;            // 8 float4 per row
    int cbase = (e4 & 7) * 4;
    int b = batch_id[node];
    float4 v = ((const float4*)out)[e4];
    float r[4] = {v.x, v.y, v.z, v.w};
    #pragma unroll
    for (int j = 0; j < 4; j++) {
        int cc = cbase + j;
        int gg = cc >> 2;
        float m  = gMean[b * GRP + gg];
        float is = gIstd[b * GRP + gg];
        float y = (r[j] - m) * is * gamma[cc] + beta[cc];
        r[j] = fmaxf(y, 0.f);
    }
    ((float4*)out)[e4] = make_float4(r[0], r[1], r[2], r[3]);
}

// ---------------- launch ----------------
extern "C" void kernel_launch(void* const* d_in, const int* in_sizes, int n_in,
                              void* d_out, int out_size)
{
    const float* data    = (const float*)d_in[0];
    const float* weights = (const float*)d_in[1];
    const float* gamma   = (const float*)d_in[2];
    const float* beta    = (const float*)d_in[3];
    const int*   neigh   = (const int*)d_in[4];
    const int*   batch   = (const int*)d_in[5];
    float*       out     = (float*)d_out;

    const int N = in_sizes[0] / CIN;

    cudaFuncSetAttribute(deconv_kernel,
                         cudaFuncAttributeMaxDynamicSharedMemorySize, SMEM_BYTES);

    zero_stats_kernel<<<1, 256>>>();

    int nblk = (N + TILE - 1) / TILE;
    deconv_kernel<<<nblk, NTHR, SMEM_BYTES>>>(data, weights, neigh, out, N);

    const int statBlocks = 592;
    const int nWarps = statBlocks * (256 / 32);
    const int span = (N + nWarps - 1) / nWarps;
    stats_kernel<<<statBlocks, 256>>>(out, batch, N, span);

    finalize_kernel<<<1, 64>>>();

    long total4 = (long)N * (COUT / 4);
    int nb2 = (int)((total4 + 255) / 256);
    norm_kernel<<<nb2, 256>>>(out, batch, gamma, beta, N);
}

// round 9
// speedup vs baseline: 2.1623x; 1.3597x over previous
#include <cuda_runtime.h>
#include <cstdint>

#define KTAPS 27
#define CIN   32
#define COUT  32
#define NTHR  256
#define NB    8      // n_batch (reference constant)
#define GRP   8
#define GEPS  1e-5f
#define GRID  152    // GB300: 152 SMs, 1 CTA/SM (smem-limited)

#define W_STRIDE 36                              // padded ci-stride -> conflict-free B frags
#define SW_WORDS (KTAPS * COUT * W_STRIDE)       // 31104
#define SX_WORDS (8 * 2 * 32 * 32)               // 8 warps x 2 slabs x 32 rows x 32 words = 16384
#define SN_WORDS (8 * 32 * KTAPS)                // 8 warps x 32 rows x 27 = 6912
#define SMEM_WORDS (SW_WORDS + SX_WORDS + SN_WORDS)
#define SMEM_BYTES (SMEM_WORDS * 4)              // 217600 B

// ---------------- device-global scratch (no allocations allowed) ----------------
__device__ float gS [NB * COUT];
__device__ float gSS[NB * COUT];
__device__ float gCnt[NB];
__device__ float gMean[NB * GRP];
__device__ float gIstd[NB * GRP];

// ---------------- small PTX helpers ----------------
__device__ __forceinline__ uint32_t f2tf32(float f) {
    uint32_t r;
    asm("cvt.rna.tf32.f32 %0, %1;" : "=r"(r) : "f"(f));
    return r;
}

__device__ __forceinline__ void mma_tf32(float* d, const uint32_t* a, uint32_t b0, uint32_t b1) {
    asm volatile(
        "mma.sync.aligned.m16n8k8.row.col.f32.tf32.tf32.f32 "
        "{%0,%1,%2,%3}, {%4,%5,%6,%7}, {%8,%9}, {%0,%1,%2,%3};"
        : "+f"(d[0]), "+f"(d[1]), "+f"(d[2]), "+f"(d[3])
        : "r"(a[0]), "r"(a[1]), "r"(a[2]), "r"(a[3]), "r"(b0), "r"(b1));
}

// ---------------- kernel 0: zero stats ----------------
__global__ void zero_stats_kernel() {
    int t = threadIdx.x;
    if (t < NB * COUT) { gS[t] = 0.f; gSS[t] = 0.f; }
    if (t < NB) gCnt[t] = 0.f;
}

// ---------------- deconv helpers ----------------
__device__ __forceinline__ void gather_tap(float4* st, const int* myN, int k,
                                           const float* __restrict__ data,
                                           int rsub, int cwrd) {
    #pragma unroll
    for (int i = 0; i < 8; i++) {
        int rl  = 4 * i + rsub;
        int idx = myN[rl * KTAPS + k];
        st[i] = *(const float4*)(data + (size_t)idx * CIN + cwrd);
    }
}

__device__ __forceinline__ void store_slab(float* slab, const float4* st,
                                           int rsub, int cwrd) {
    #pragma unroll
    for (int i = 0; i < 8; i++) {
        int rl   = 4 * i + rsub;
        int colw = cwrd ^ (4 * (rl & 7));   // XOR swizzle -> conflict-free STS/LDS
        *(float4*)(slab + rl * 32 + colw) = st[i];
    }
}

__device__ __forceinline__ void mma_tap(const float* slab, const uint32_t* wk,
                                        int g, int c, float acc[2][4][4]) {
    const uint32_t* xw = (const uint32_t*)slab;
    const int sw = 4 * g;
    #pragma unroll
    for (int kc = 0; kc < 4; kc++) {
        const int colA  = (kc * 8 + c)     ^ sw;
        const int colA2 = (kc * 8 + c + 4) ^ sw;
        uint32_t a[2][4];
        #pragma unroll
        for (int m = 0; m < 2; m++) {
            int r0 = g + 16 * m;
            a[m][0] = xw[(r0    ) * 32 + colA ];
            a[m][1] = xw[(r0 + 8) * 32 + colA ];
            a[m][2] = xw[(r0    ) * 32 + colA2];
            a[m][3] = xw[(r0 + 8) * 32 + colA2];
        }
        #pragma unroll
        for (int nt = 0; nt < 4; nt++) {
            uint32_t b0 = wk[(nt * 8 + g) * W_STRIDE + kc * 8 + c    ];
            uint32_t b1 = wk[(nt * 8 + g) * W_STRIDE + kc * 8 + c + 4];
            mma_tf32(acc[0][nt], a[0], b0, b1);
            mma_tf32(acc[1][nt], a[1], b0, b1);
        }
    }
}

// ---------------- kernel 1: persistent deconv + fused GN stats ----------------
// Warp-persistent: each warp independently processes 32-row chunks (grid-stride).
// Depth-2 LDG pipeline (stA/stB register sets) + double-buffered smem slab.
// Epilogue writes pre-norm h to out and accumulates per-(batch,cout) sum/sumsq
// via warp butterfly reduce + global atomics (fast path: chunk in one batch).
__global__ __launch_bounds__(NTHR, 1)
void deconv_kernel(const float* __restrict__ data,
                   const float* __restrict__ weights,
                   const int*   __restrict__ neigh,
                   const int*   __restrict__ batch_id,
                   float* __restrict__ out, int N, int nchunks)
{
    extern __shared__ float smem[];
    uint32_t* sW = (uint32_t*)smem;                 // [27][co=32][ci stride 36], tf32
    float*    sX = smem + SW_WORDS;                 // 8 warps x 2 slabs x 32x32
    int*      sN = (int*)(smem + SW_WORDS + SX_WORDS);

    const int tid  = threadIdx.x;
    const int lane = tid & 31;
    const int warp = tid >> 5;

    // ---- stage weights once per CTA: [k][ci][co] -> [k][co][ci], tf32 ----
    const float4* w4 = (const float4*)weights;
    for (int q = tid; q < (KTAPS * CIN * COUT) / 4; q += NTHR) {
        float4 v = w4[q];
        int lin = q * 4;
        int k  = lin >> 10;
        int r  = lin & 1023;
        int ci = r >> 5;
        int co = r & 31;
        uint32_t* dst = sW + k * (COUT * W_STRIDE) + ci;
        dst[(co + 0) * W_STRIDE] = f2tf32(v.x);
        dst[(co + 1) * W_STRIDE] = f2tf32(v.y);
        dst[(co + 2) * W_STRIDE] = f2tf32(v.z);
        dst[(co + 3) * W_STRIDE] = f2tf32(v.w);
    }
    __syncthreads();

    const int g    = lane >> 2;         // 0..7
    const int c    = lane & 3;          // 0..3
    const int rsub = lane >> 3;         // 0..3
    const int cwrd = (lane & 7) * 4;    // 0,4,...,28
    float* slab0 = sX + warp * 2048;
    float* slab1 = slab0 + 1024;
    int*   myN   = sN + warp * (32 * KTAPS);

    for (int chunk = blockIdx.x * 8 + warp; chunk < nchunks; chunk += GRID * 8) {
        const int rowStart = chunk * 32;
        const int valid = min(32, N - rowStart);

        // ---- stage this chunk's neighbor table (coalesced, per-warp) ----
        const int nlim = valid * KTAPS;
        #pragma unroll
        for (int i = 0; i < KTAPS; i++) {
            int j = i * 32 + lane;
            myN[j] = (j < nlim) ? neigh[rowStart * KTAPS + j] : 0;
        }
        __syncwarp();

        float acc[2][4][4];
        #pragma unroll
        for (int m = 0; m < 2; m++)
            #pragma unroll
            for (int nt = 0; nt < 4; nt++)
                #pragma unroll
                for (int j = 0; j < 4; j++) acc[m][nt][j] = 0.f;

        float4 stA[8], stB[8];
        gather_tap(stA, myN, 0, data, rsub, cwrd);
        gather_tap(stB, myN, 1, data, rsub, cwrd);

        // ---- tap pairs 0..25, depth-2 pipeline ----
        for (int k = 0; k < 26; k += 2) {
            store_slab(slab0, stA, rsub, cwrd);
            gather_tap(stA, myN, k + 2, data, rsub, cwrd);        // k+2 <= 26
            __syncwarp();
            mma_tap(slab0, sW + k * (COUT * W_STRIDE), g, c, acc);

            store_slab(slab1, stB, rsub, cwrd);
            if (k + 3 < KTAPS)
                gather_tap(stB, myN, k + 3, data, rsub, cwrd);
            __syncwarp();
            mma_tap(slab1, sW + (k + 1) * (COUT * W_STRIDE), g, c, acc);
        }
        // tail tap 26
        store_slab(slab0, stA, rsub, cwrd);
        __syncwarp();
        mma_tap(slab0, sW + 26 * (COUT * W_STRIDE), g, c, acc);
        __syncwarp();

        // ---- epilogue: write h ----
        #pragma unroll
        for (int m = 0; m < 2; m++) {
            int r0 = g + 16 * m;
            #pragma unroll
            for (int nt = 0; nt < 4; nt++) {
                int colp  = nt * 8 + 2 * c;
                int node0 = rowStart + r0;
                int node1 = node0 + 8;
                if (node0 < N)
                    *(float2*)(out + (size_t)node0 * COUT + colp) =
                        make_float2(acc[m][nt][0], acc[m][nt][1]);
                if (node1 < N)
                    *(float2*)(out + (size_t)node1 * COUT + colp) =
                        make_float2(acc[m][nt][2], acc[m][nt][3]);
            }
        }

        // ---- fused GN stats ----
        int rlast  = min(rowStart + 31, N - 1);
        int bFirst = batch_id[rowStart];
        int bLast  = batch_id[rlast];
        if (bFirst == bLast && rowStart + 32 <= N) {
            // fast path: whole chunk in one octree
            #pragma unroll
            for (int nt = 0; nt < 4; nt++) {
                float s0 = 0.f, s1 = 0.f, q0 = 0.f, q1 = 0.f;
                #pragma unroll
                for (int m = 0; m < 2; m++) {
                    float v;
                    v = acc[m][nt][0]; s0 += v; q0 += v * v;
                    v = acc[m][nt][2]; s0 += v; q0 += v * v;
                    v = acc[m][nt][1]; s1 += v; q1 += v * v;
                    v = acc[m][nt][3]; s1 += v; q1 += v * v;
                }
                #pragma unroll
                for (int o = 4; o <= 16; o <<= 1) {
                    s0 += __shfl_xor_sync(0xffffffffu, s0, o);
                    q0 += __shfl_xor_sync(0xffffffffu, q0, o);
                    s1 += __shfl_xor_sync(0xffffffffu, s1, o);
                    q1 += __shfl_xor_sync(0xffffffffu, q1, o);
                }
                if (lane < 4) {
                    int co0 = nt * 8 + 2 * c;
                    atomicAdd(&gS [bFirst * COUT + co0    ], s0);
                    atomicAdd(&gS [bFirst * COUT + co0 + 1], s1);
                    atomicAdd(&gSS[bFirst * COUT + co0    ], q0);
                    atomicAdd(&gSS[bFirst * COUT + co0 + 1], q1);
                }
            }
            if (lane == 0) atomicAdd(&gCnt[bFirst], 32.f);
        } else {
            // slow path: batch boundary (rare) — per-row atomics
            #pragma unroll
            for (int m = 0; m < 2; m++) {
                int r0 = rowStart + g + 16 * m;
                int r1 = r0 + 8;
                #pragma unroll
                for (int nt = 0; nt < 4; nt++) {
                    int co0 = nt * 8 + 2 * c;
                    if (r0 < N) {
                        int b = batch_id[r0];
                        float v0 = acc[m][nt][0], v1 = acc[m][nt][1];
                        atomicAdd(&gS [b * COUT + co0    ], v0);
                        atomicAdd(&gS [b * COUT + co0 + 1], v1);
                        atomicAdd(&gSS[b * COUT + co0    ], v0 * v0);
                        atomicAdd(&gSS[b * COUT + co0 + 1], v1 * v1);
                    }
                    if (r1 < N) {
                        int b = batch_id[r1];
                        float v0 = acc[m][nt][2], v1 = acc[m][nt][3];
                        atomicAdd(&gS [b * COUT + co0    ], v0);
                        atomicAdd(&gS [b * COUT + co0 + 1], v1);
                        atomicAdd(&gSS[b * COUT + co0    ], v0 * v0);
                        atomicAdd(&gSS[b * COUT + co0 + 1], v1 * v1);
                    }
                }
            }
            if (lane < valid) atomicAdd(&gCnt[batch_id[rowStart + lane]], 1.f);
        }
        __syncwarp();
    }
}

// ---------------- kernel 3: finalize group stats (ocnn OctreeGroupNorm math) ----------------
__global__ void finalize_kernel() {
    int t = threadIdx.x;
    if (t >= NB * GRP) return;
    int b = t >> 3, g = t & 7;
    float S = 0.f, SS = 0.f;
    #pragma unroll
    for (int j = 0; j < 4; j++) {
        S  += gS [b * COUT + g * 4 + j];
        SS += gSS[b * COUT + g * 4 + j];
    }
    float cntf = gCnt[b] * ((float)COUT / (float)GRP);   // n_nodes * C/G
    float inv  = 1.f / (cntf + GEPS);
    float mean = S * inv;
    float var  = (SS - 2.f * mean * S + cntf * mean * mean) * inv;
    gMean[t] = mean;
    gIstd[t] = rsqrtf(var + GEPS);
}

// ---------------- kernel 4: normalize + affine + relu (in-place) ----------------
__global__ void norm_kernel(float* __restrict__ out,
                            const int* __restrict__ batch_id,
                            const float* __restrict__ gamma,
                            const float* __restrict__ beta,
                            int N)
{
    int e4 = blockIdx.x * blockDim.x + threadIdx.x;   // float4 index
    long total4 = (long)N * (COUT / 4);
    if (e4 >= total4) return;
    int node  = e4 >> 3;            // 8 float4 per row
    int cbase = (e4 & 7) * 4;
    int b = batch_id[node];
    float4 v = ((const float4*)out)[e4];
    float r[4] = {v.x, v.y, v.z, v.w};
    #pragma unroll
    for (int j = 0; j < 4; j++) {
        int cc = cbase + j;
        int gg = cc >> 2;
        float m  = gMean[b * GRP + gg];
        float is = gIstd[b * GRP + gg];
        float y = (r[j] - m) * is * gamma[cc] + beta[cc];
        r[j] = fmaxf(y, 0.f);
    }
    ((float4*)out)[e4] = make_float4(r[0], r[1], r[2], r[3]);
}

// ---------------- launch ----------------
extern "C" void kernel_launch(void* const* d_in, const int* in_sizes, int n_in,
                              void* d_out, int out_size)
{
    const float* data    = (const float*)d_in[0];
    const float* weights = (const float*)d_in[1];
    const float* gamma   = (const float*)d_in[2];
    const float* beta    = (const float*)d_in[3];
    const int*   neigh   = (const int*)d_in[4];
    const int*   batch   = (const int*)d_in[5];
    float*       out     = (float*)d_out;

    const int N = in_sizes[0] / CIN;
    const int nchunks = (N + 31) / 32;

    cudaFuncSetAttribute(deconv_kernel,
                         cudaFuncAttributeMaxDynamicSharedMemorySize, SMEM_BYTES);

    zero_stats_kernel<<<1, 256>>>();

    deconv_kernel<<<GRID, NTHR, SMEM_BYTES>>>(data, weights, neigh, batch, out, N, nchunks);

    finalize_kernel<<<1, 64>>>();

    long total4 = (long)N * (COUT / 4);
    int nb2 = (int)((total4 + 255) / 256);
    norm_kernel<<<nb2, 256>>>(out, batch, gamma, beta, N);
}